// round 5
// baseline (speedup 1.0000x reference)
#include <cuda_runtime.h>
#include <math.h>

// Problem constants (fixed shapes from reference setup_inputs)
#define BATCH 4
#define NPTS  8192
#define ALPHA 1000.0f

// 2D column grid on (x,y): 64x64 cells of width 0.125 covering [-4,4), clamped
#define GDIM   64
#define CELLW  0.125f
#define NCOL   (GDIM * GDIM)     // 4096 columns per point set

// ---------------------------------------------------------------------------
// Scratch (__device__ globals; no allocation allowed)
// arr index a: 0 = xyz1 (pred), 1 = xyz2 (gt)
// ---------------------------------------------------------------------------
__device__ float4 g_pts   [2][BATCH][NPTS];      // column-sorted (x,y,z,|p|^2)
__device__ int    g_orig  [2][BATCH][NPTS];      // sorted pos -> original index
__device__ int    g_colid [2][BATCH][NPTS];      // original index -> column
__device__ int    g_hist  [2][BATCH][NCOL];
__device__ int    g_start [2][BATCH][NCOL + 1];
__device__ int    g_cursor[2][BATCH][NCOL];
// dir 0: queries = xyz2 (gt), refs = xyz1 (pred); dir 1: swapped
__device__ float  g_dist[2][BATCH][NPTS];
__device__ int    g_idx [2][BATCH][NPTS];
__device__ int    g_cnt [2][BATCH][NPTS];

__device__ __forceinline__ int cell_coord(float x) {
    int c = (int)floorf(x * 8.0f) + 32;      // W = 0.125, origin -4
    return min(GDIM - 1, max(0, c));
}

// ---------------------------------------------------------------------------
// K0: zero histograms, counts, output
// ---------------------------------------------------------------------------
__global__ void dacd_zero_kernel(float* __restrict__ out) {
    int t = blockIdx.x * blockDim.x + threadIdx.x;
    if (t < 2 * BATCH * NPTS) ((int*)g_cnt)[t] = 0;
    if (t < 2 * BATCH * NCOL) ((int*)g_hist)[t] = 0;
    if (t == 0) out[0] = 0.0f;
}

// ---------------------------------------------------------------------------
// K1: column ids + histogram
// ---------------------------------------------------------------------------
__global__ void dacd_hist_kernel(const float* __restrict__ xyz1,
                                 const float* __restrict__ xyz2) {
    int t = blockIdx.x * blockDim.x + threadIdx.x;
    if (t >= 2 * BATCH * NPTS) return;
    const int a   = t / (BATCH * NPTS);
    const int rem = t % (BATCH * NPTS);
    const int b   = rem / NPTS;
    const int j   = rem % NPTS;
    const float* src = (a == 0) ? xyz1 : xyz2;
    float x = src[((size_t)b * NPTS + j) * 3 + 0];
    float y = src[((size_t)b * NPTS + j) * 3 + 1];
    int col = cell_coord(x) * GDIM + cell_coord(y);
    g_colid[a][b][j] = col;
    atomicAdd(&g_hist[a][b][col], 1);
}

// ---------------------------------------------------------------------------
// K2: exclusive scan of 4096-entry histogram per set (8 blocks x 1024 thr)
// ---------------------------------------------------------------------------
__global__ void __launch_bounds__(1024)
dacd_scan_kernel() {
    const int a = blockIdx.x >> 2;
    const int b = blockIdx.x & 3;
    const int tid = threadIdx.x;
    __shared__ int sh[1024];

    int h[4];
    int tot = 0;
    #pragma unroll
    for (int i = 0; i < 4; i++) {
        h[i] = g_hist[a][b][tid * 4 + i];
        tot += h[i];
    }
    sh[tid] = tot;
    __syncthreads();
    #pragma unroll
    for (int off = 1; off < 1024; off <<= 1) {
        int v = (tid >= off) ? sh[tid - off] : 0;
        __syncthreads();
        sh[tid] += v;
        __syncthreads();
    }
    int base = sh[tid] - tot;   // exclusive prefix of this thread's 4 cells
    #pragma unroll
    for (int i = 0; i < 4; i++) {
        g_start [a][b][tid * 4 + i] = base;
        g_cursor[a][b][tid * 4 + i] = base;
        base += h[i];
    }
    if (tid == 1023) g_start[a][b][NCOL] = base;   // == NPTS
}

// ---------------------------------------------------------------------------
// K3: scatter points into column-sorted order
// ---------------------------------------------------------------------------
__global__ void dacd_scatter_kernel(const float* __restrict__ xyz1,
                                    const float* __restrict__ xyz2) {
    int t = blockIdx.x * blockDim.x + threadIdx.x;
    if (t >= 2 * BATCH * NPTS) return;
    const int a   = t / (BATCH * NPTS);
    const int rem = t % (BATCH * NPTS);
    const int b   = rem / NPTS;
    const int j   = rem % NPTS;
    const float* src = (a == 0) ? xyz1 : xyz2;
    float x = src[((size_t)b * NPTS + j) * 3 + 0];
    float y = src[((size_t)b * NPTS + j) * 3 + 1];
    float z = src[((size_t)b * NPTS + j) * 3 + 2];
    int col = g_colid[a][b][j];
    int pos = atomicAdd(&g_cursor[a][b][col], 1);
    g_pts [a][b][pos] = make_float4(x, y, z, x * x + y * y + z * z);
    g_orig[a][b][pos] = j;
}

// ---------------------------------------------------------------------------
// K4: exact NN via expanding column rings, warp-shared candidate scan.
// Each warp: 32 consecutive sorted queries (compact column box). All lanes
// scan the SAME contiguous point runs (no divergence, broadcast loads).
// After ring k, unscanned columns are >= k*CELLW away from the box in x or y,
// and every query lies inside the box, so d_true >= (k*CELLW)^2 for all
// unscanned points (clamped columns only push points farther). Stop when all
// lanes have bestd <= (k*W)^2 - margin. Same FFMA expression as brute force.
// ---------------------------------------------------------------------------
__global__ void __launch_bounds__(256)
dacd_nn_kernel() {
    const int lane  = threadIdx.x & 31;
    const int W     = blockIdx.x * 8 + (threadIdx.x >> 5);   // 0..2047
    const int dir   = W >> 10;
    const int b     = (W >> 8) & 3;
    const int chunk = W & 255;
    const int qarr  = 1 - dir;   // dir0 queries = xyz2 (arr 1)
    const int rarr  = dir;       // dir0 refs    = xyz1 (arr 0)

    const int si = chunk * 32 + lane;
    const float4 q  = g_pts [qarr][b][si];
    const int    oi = g_orig[qarr][b][si];
    const float mx = -2.0f * q.x, my = -2.0f * q.y, mz = -2.0f * q.z;

    const int qcx = cell_coord(q.x);
    const int qcy = cell_coord(q.y);
    const int bx0 = (int)__reduce_min_sync(0xFFFFFFFFu, (unsigned)qcx);
    const int bx1 = (int)__reduce_max_sync(0xFFFFFFFFu, (unsigned)qcx);
    const int by0 = (int)__reduce_min_sync(0xFFFFFFFFu, (unsigned)qcy);
    const int by1 = (int)__reduce_max_sync(0xFFFFFFFFu, (unsigned)qcy);

    const float4* __restrict__ refs = &g_pts  [rarr][b][0];
    const int*    __restrict__ cs   = &g_start[rarr][b][0];

    float bestd = INFINITY;   // d' = |r|^2 - 2 q.r
    int   bestt = 0;          // sorted position of current best

    auto scan_run = [&](int cx, int y0, int y1) {
        const int s = cs[cx * GDIM + y0];
        const int e = cs[cx * GDIM + y1 + 1];
        #pragma unroll 4
        for (int t = s; t < e; t++) {
            float4 v = __ldg(&refs[t]);
            float d = fmaf(mx, v.x, fmaf(my, v.y, fmaf(mz, v.z, v.w)));
            if (d < bestd) { bestd = d; bestt = t; }
        }
    };

    #pragma unroll 1
    for (int k = 0; k < GDIM; k++) {
        const int xlo = max(bx0 - k, 0), xhi = min(bx1 + k, GDIM - 1);
        const int ylo = max(by0 - k, 0), yhi = min(by1 + k, GDIM - 1);
        #pragma unroll 1
        for (int cx = xlo; cx <= xhi; cx++) {
            const int dx = max(max(bx0 - cx, cx - bx1), 0);
            if (dx == k) {
                scan_run(cx, ylo, yhi);          // full new column run
            } else {
                if (by0 - k >= 0)     scan_run(cx, by0 - k, by0 - k);
                if (by1 + k <= GDIM - 1) scan_run(cx, by1 + k, by1 + k);
            }
        }
        const float kb = (float)k * CELLW;
        const bool done = (q.w + bestd) <= (kb * kb - 1e-4f);
        if (__all_sync(0xFFFFFFFFu, done)) break;
        if (xlo == 0 && ylo == 0 && xhi == GDIM - 1 && yhi == GDIM - 1) break;
    }

    const int bj = g_orig[rarr][b][bestt];
    g_dist[dir][b][oi] = q.w + bestd;
    g_idx [dir][b][oi] = bj;
    atomicAdd(&g_cnt[dir][b][bj], 1);
}

// ---------------------------------------------------------------------------
// K5: density-aware weighting + reduction to scalar.
// frac_21 = 1.0 exactly; ceil(frac_21) = 1.
// weight1 = 1 / max(1/c + 1e-6, 1),  weight2 = 1 / (c + 1e-6)
// out = sum (1 - exp(-alpha*d) * w) / (2*B*N)
// ---------------------------------------------------------------------------
__global__ void __launch_bounds__(256)
dacd_loss_kernel(float* __restrict__ out) {
    const int t = blockIdx.x * blockDim.x + threadIdx.x;
    const int dir = t / (BATCH * NPTS);
    const int rem = t % (BATCH * NPTS);
    const int b = rem / NPTS;
    const int i = rem % NPTS;

    float dist = g_dist[dir][b][i];
    int   idx  = g_idx [dir][b][i];
    float c    = (float)g_cnt[dir][b][idx];

    float w;
    if (dir == 0) {
        w = 1.0f / fmaxf(1.0f / c + 1e-6f, 1.0f);
    } else {
        w = 1.0f / (c + 1e-6f);
    }

    float e = expf(-dist * ALPHA);
    float contrib = (1.0f - e * w) * (1.0f / (2.0f * BATCH * NPTS));

    #pragma unroll
    for (int off = 16; off > 0; off >>= 1)
        contrib += __shfl_down_sync(0xFFFFFFFFu, contrib, off);

    __shared__ float warp_sums[8];
    const int lane = threadIdx.x & 31;
    const int wid  = threadIdx.x >> 5;
    if (lane == 0) warp_sums[wid] = contrib;
    __syncthreads();

    if (wid == 0) {
        float s = (lane < 8) ? warp_sums[lane] : 0.0f;
        #pragma unroll
        for (int off = 4; off > 0; off >>= 1)
            s += __shfl_down_sync(0xFFFFFFFFu, s, off);
        if (lane == 0) atomicAdd(out, s);
    }
}

// ---------------------------------------------------------------------------
// Launch
// ---------------------------------------------------------------------------
extern "C" void kernel_launch(void* const* d_in, const int* in_sizes, int n_in,
                              void* d_out, int out_size) {
    const float* xyz1 = (const float*)d_in[0];  // prediction [4,8192,3]
    const float* xyz2 = (const float*)d_in[1];  // ground truth [4,8192,3]
    float* out = (float*)d_out;

    (void)in_sizes; (void)n_in; (void)out_size;

    const int total = 2 * BATCH * NPTS;          // 65536

    dacd_zero_kernel   <<<(total + 255) / 256, 256>>>(out);
    dacd_hist_kernel   <<<(total + 255) / 256, 256>>>(xyz1, xyz2);
    dacd_scan_kernel   <<<2 * BATCH, 1024>>>();
    dacd_scatter_kernel<<<(total + 255) / 256, 256>>>(xyz1, xyz2);

    dacd_nn_kernel<<<256, 256>>>();              // 2048 warps, 32 queries each

    dacd_loss_kernel<<<total / 256, 256>>>(out);
}

// round 6
// speedup vs baseline: 1.4065x; 1.4065x over previous
#include <cuda_runtime.h>
#include <math.h>

// Problem constants (fixed shapes from reference setup_inputs)
#define BATCH 4
#define NPTS  8192
#define ALPHA 1000.0f

// 2D column grid on (x,y): 64x64 cells of width 0.125 covering [-4,4), clamped.
// Columns ordered SERPENTINE: serp(cx,cy) = cx*64 + (cx odd ? 63-cy : cy),
// so consecutive sorted points never jump in y at x-row crossings.
#define GDIM   64
#define CELLW  0.125f
#define NCOL   (GDIM * GDIM)     // 4096 columns per point set

// ---------------------------------------------------------------------------
// Scratch (__device__ globals; no allocation allowed)
// arr index a: 0 = xyz1 (pred), 1 = xyz2 (gt)
// ---------------------------------------------------------------------------
__device__ float4 g_pts   [2][BATCH][NPTS];      // column-sorted (x,y,z,|p|^2)
__device__ int    g_orig  [2][BATCH][NPTS];      // sorted pos -> original index
__device__ int    g_colid [2][BATCH][NPTS];      // original index -> serp column
__device__ int    g_hist  [2][BATCH][NCOL];
__device__ int    g_start [2][BATCH][NCOL + 1];
__device__ int    g_cursor[2][BATCH][NCOL];
// dir 0: queries = xyz2 (gt), refs = xyz1 (pred); dir 1: swapped
__device__ float  g_dist[2][BATCH][NPTS];
__device__ int    g_idx [2][BATCH][NPTS];
__device__ int    g_cnt [2][BATCH][NPTS];

__device__ __forceinline__ int cell_coord(float x) {
    int c = (int)floorf(x * 8.0f) + 32;      // W = 0.125, origin -4
    return min(GDIM - 1, max(0, c));
}
__device__ __forceinline__ int serp_col(int cx, int cy) {
    return cx * GDIM + ((cx & 1) ? (GDIM - 1 - cy) : cy);
}

// ---------------------------------------------------------------------------
// K0: zero histograms, counts, output
// ---------------------------------------------------------------------------
__global__ void dacd_zero_kernel(float* __restrict__ out) {
    int t = blockIdx.x * blockDim.x + threadIdx.x;
    if (t < 2 * BATCH * NPTS) ((int*)g_cnt)[t] = 0;
    if (t < 2 * BATCH * NCOL) ((int*)g_hist)[t] = 0;
    if (t == 0) out[0] = 0.0f;
}

// ---------------------------------------------------------------------------
// K1: serpentine column ids + histogram
// ---------------------------------------------------------------------------
__global__ void dacd_hist_kernel(const float* __restrict__ xyz1,
                                 const float* __restrict__ xyz2) {
    int t = blockIdx.x * blockDim.x + threadIdx.x;
    if (t >= 2 * BATCH * NPTS) return;
    const int a   = t / (BATCH * NPTS);
    const int rem = t % (BATCH * NPTS);
    const int b   = rem / NPTS;
    const int j   = rem % NPTS;
    const float* src = (a == 0) ? xyz1 : xyz2;
    float x = src[((size_t)b * NPTS + j) * 3 + 0];
    float y = src[((size_t)b * NPTS + j) * 3 + 1];
    int col = serp_col(cell_coord(x), cell_coord(y));
    g_colid[a][b][j] = col;
    atomicAdd(&g_hist[a][b][col], 1);
}

// ---------------------------------------------------------------------------
// K2: exclusive scan of 4096-entry histogram per set (8 blocks x 1024 thr)
// ---------------------------------------------------------------------------
__global__ void __launch_bounds__(1024)
dacd_scan_kernel() {
    const int a = blockIdx.x >> 2;
    const int b = blockIdx.x & 3;
    const int tid = threadIdx.x;
    __shared__ int sh[1024];

    int h[4];
    int tot = 0;
    #pragma unroll
    for (int i = 0; i < 4; i++) {
        h[i] = g_hist[a][b][tid * 4 + i];
        tot += h[i];
    }
    sh[tid] = tot;
    __syncthreads();
    #pragma unroll
    for (int off = 1; off < 1024; off <<= 1) {
        int v = (tid >= off) ? sh[tid - off] : 0;
        __syncthreads();
        sh[tid] += v;
        __syncthreads();
    }
    int base = sh[tid] - tot;
    #pragma unroll
    for (int i = 0; i < 4; i++) {
        g_start [a][b][tid * 4 + i] = base;
        g_cursor[a][b][tid * 4 + i] = base;
        base += h[i];
    }
    if (tid == 1023) g_start[a][b][NCOL] = base;   // == NPTS
}

// ---------------------------------------------------------------------------
// K3: scatter points into serpentine-column-sorted order
// ---------------------------------------------------------------------------
__global__ void dacd_scatter_kernel(const float* __restrict__ xyz1,
                                    const float* __restrict__ xyz2) {
    int t = blockIdx.x * blockDim.x + threadIdx.x;
    if (t >= 2 * BATCH * NPTS) return;
    const int a   = t / (BATCH * NPTS);
    const int rem = t % (BATCH * NPTS);
    const int b   = rem / NPTS;
    const int j   = rem % NPTS;
    const float* src = (a == 0) ? xyz1 : xyz2;
    float x = src[((size_t)b * NPTS + j) * 3 + 0];
    float y = src[((size_t)b * NPTS + j) * 3 + 1];
    float z = src[((size_t)b * NPTS + j) * 3 + 2];
    int col = g_colid[a][b][j];
    int pos = atomicAdd(&g_cursor[a][b][col], 1);
    g_pts [a][b][pos] = make_float4(x, y, z, x * x + y * y + z * z);
    g_orig[a][b][pos] = j;
}

// ---------------------------------------------------------------------------
// K4: exact NN via expanding column rings, warp-shared candidate scan.
// Each warp: 32 consecutive sorted queries. Serpentine order keeps the warp's
// cell bounding box compact (~2x2) even across x-row crossings. All lanes scan
// the SAME contiguous sorted runs (one run per x-row of the ring; a y-range
// within row cx is contiguous in serpentine order, reversed for odd cx).
// After ring k, every unscanned point is >= k*CELLW away in x or y from the
// box (clamped cells only push points farther), and all queries lie in the
// box, so unscanned d_true >= (k*CELLW)^2. Stop when all lanes are done.
// Same FFMA expression as brute force -> bitwise-identical min values.
// ---------------------------------------------------------------------------
__global__ void __launch_bounds__(256)
dacd_nn_kernel() {
    const int lane  = threadIdx.x & 31;
    const int W     = blockIdx.x * 8 + (threadIdx.x >> 5);   // 0..2047
    const int dir   = W >> 10;
    const int b     = (W >> 8) & 3;
    const int chunk = W & 255;
    const int qarr  = 1 - dir;   // dir0 queries = xyz2 (arr 1)
    const int rarr  = dir;       // dir0 refs    = xyz1 (arr 0)

    const int si = chunk * 32 + lane;
    const float4 q  = g_pts [qarr][b][si];
    const int    oi = g_orig[qarr][b][si];
    const float mx = -2.0f * q.x, my = -2.0f * q.y, mz = -2.0f * q.z;

    const int qcx = cell_coord(q.x);
    const int qcy = cell_coord(q.y);
    const int bx0 = (int)__reduce_min_sync(0xFFFFFFFFu, (unsigned)qcx);
    const int bx1 = (int)__reduce_max_sync(0xFFFFFFFFu, (unsigned)qcx);
    const int by0 = (int)__reduce_min_sync(0xFFFFFFFFu, (unsigned)qcy);
    const int by1 = (int)__reduce_max_sync(0xFFFFFFFFu, (unsigned)qcy);

    const float4* __restrict__ refs = &g_pts  [rarr][b][0];
    const int*    __restrict__ cs   = &g_start[rarr][b][0];

    float bestd = INFINITY;   // d' = |r|^2 - 2 q.r
    int   bestt = 0;          // sorted position of current best

    auto scan_run = [&](int cx, int y0, int y1) {
        int lo, hi;
        if (cx & 1) { lo = cx * GDIM + (GDIM - 1 - y1); hi = cx * GDIM + (GDIM - 1 - y0); }
        else        { lo = cx * GDIM + y0;              hi = cx * GDIM + y1; }
        const int s = cs[lo];
        const int e = cs[hi + 1];
        #pragma unroll 4
        for (int t = s; t < e; t++) {
            float4 v = __ldg(&refs[t]);
            float d = fmaf(mx, v.x, fmaf(my, v.y, fmaf(mz, v.z, v.w)));
            if (d < bestd) { bestd = d; bestt = t; }
        }
    };

    #pragma unroll 1
    for (int k = 0; k < GDIM; k++) {
        const int xlo = max(bx0 - k, 0), xhi = min(bx1 + k, GDIM - 1);
        const int ylo = max(by0 - k, 0), yhi = min(by1 + k, GDIM - 1);
        #pragma unroll 1
        for (int cx = xlo; cx <= xhi; cx++) {
            const int dx = max(max(bx0 - cx, cx - bx1), 0);
            if (dx == k) {
                scan_run(cx, ylo, yhi);          // entirely-new column run
            } else {
                if (by0 - k >= 0)        scan_run(cx, by0 - k, by0 - k);
                if (by1 + k <= GDIM - 1) scan_run(cx, by1 + k, by1 + k);
            }
        }
        const float kb = (float)k * CELLW;
        const bool done = (q.w + bestd) <= (kb * kb - 1e-4f);
        if (__all_sync(0xFFFFFFFFu, done)) break;
        if (xlo == 0 && ylo == 0 && xhi == GDIM - 1 && yhi == GDIM - 1) break;
    }

    const int bj = g_orig[rarr][b][bestt];
    g_dist[dir][b][oi] = q.w + bestd;
    g_idx [dir][b][oi] = bj;
    atomicAdd(&g_cnt[dir][b][bj], 1);
}

// ---------------------------------------------------------------------------
// K5: density-aware weighting + reduction to scalar.
// frac_21 = 1.0 exactly; ceil(frac_21) = 1.
// weight1 = 1 / max(1/c + 1e-6, 1),  weight2 = 1 / (c + 1e-6)
// out = sum (1 - exp(-alpha*d) * w) / (2*B*N)
// ---------------------------------------------------------------------------
__global__ void __launch_bounds__(256)
dacd_loss_kernel(float* __restrict__ out) {
    const int t = blockIdx.x * blockDim.x + threadIdx.x;
    const int dir = t / (BATCH * NPTS);
    const int rem = t % (BATCH * NPTS);
    const int b = rem / NPTS;
    const int i = rem % NPTS;

    float dist = g_dist[dir][b][i];
    int   idx  = g_idx [dir][b][i];
    float c    = (float)g_cnt[dir][b][idx];

    float w;
    if (dir == 0) {
        w = 1.0f / fmaxf(1.0f / c + 1e-6f, 1.0f);
    } else {
        w = 1.0f / (c + 1e-6f);
    }

    float e = expf(-dist * ALPHA);
    float contrib = (1.0f - e * w) * (1.0f / (2.0f * BATCH * NPTS));

    #pragma unroll
    for (int off = 16; off > 0; off >>= 1)
        contrib += __shfl_down_sync(0xFFFFFFFFu, contrib, off);

    __shared__ float warp_sums[8];
    const int lane = threadIdx.x & 31;
    const int wid  = threadIdx.x >> 5;
    if (lane == 0) warp_sums[wid] = contrib;
    __syncthreads();

    if (wid == 0) {
        float s = (lane < 8) ? warp_sums[lane] : 0.0f;
        #pragma unroll
        for (int off = 4; off > 0; off >>= 1)
            s += __shfl_down_sync(0xFFFFFFFFu, s, off);
        if (lane == 0) atomicAdd(out, s);
    }
}

// ---------------------------------------------------------------------------
// Launch
// ---------------------------------------------------------------------------
extern "C" void kernel_launch(void* const* d_in, const int* in_sizes, int n_in,
                              void* d_out, int out_size) {
    const float* xyz1 = (const float*)d_in[0];  // prediction [4,8192,3]
    const float* xyz2 = (const float*)d_in[1];  // ground truth [4,8192,3]
    float* out = (float*)d_out;

    (void)in_sizes; (void)n_in; (void)out_size;

    const int total = 2 * BATCH * NPTS;          // 65536

    dacd_zero_kernel   <<<(total + 255) / 256, 256>>>(out);
    dacd_hist_kernel   <<<(total + 255) / 256, 256>>>(xyz1, xyz2);
    dacd_scan_kernel   <<<2 * BATCH, 1024>>>();
    dacd_scatter_kernel<<<(total + 255) / 256, 256>>>(xyz1, xyz2);

    dacd_nn_kernel<<<256, 256>>>();              // 2048 warps, 32 queries each

    dacd_loss_kernel<<<total / 256, 256>>>(out);
}

// round 7
// speedup vs baseline: 2.1874x; 1.5552x over previous
#include <cuda_runtime.h>
#include <math.h>

// Problem constants (fixed shapes from reference setup_inputs)
#define BATCH 4
#define NPTS  8192
#define ALPHA 1000.0f

// 2D serpentine column grid on (x,y): 64x64 cells of width 0.125 on [-4,4).
#define GDIM   64
#define CELLW  0.125f
#define NCOL   (GDIM * GDIM)
#define KRECT  2                      // rectangle expansion (cells)
#define BOUND  (KRECT * CELLW * KRECT * CELLW)   // 0.0625

// ---------------------------------------------------------------------------
// Scratch (__device__ globals; no allocation allowed)
// arr index a: 0 = xyz1 (pred), 1 = xyz2 (gt)
// ---------------------------------------------------------------------------
__device__ float4 g_pts   [2][BATCH][NPTS];      // column-sorted (x,y,z,|p|^2)
__device__ int    g_orig  [2][BATCH][NPTS];
__device__ int    g_colid [2][BATCH][NPTS];
__device__ int    g_hist  [2][BATCH][NCOL];
__device__ int    g_start [2][BATCH][NCOL + 1];
__device__ int    g_cursor[2][BATCH][NCOL];
// dir 0: queries = xyz2 (gt), refs = xyz1 (pred); dir 1: swapped
__device__ float  g_dist[2][BATCH][NPTS];
__device__ int    g_idx [2][BATCH][NPTS];
__device__ int    g_cnt [2][BATCH][NPTS];
// fallback queue: packed (dir<<15 | b<<13 | si)
__device__ int    g_fbq[2 * BATCH * NPTS];
__device__ int    g_fbn;

__device__ __forceinline__ int cell_coord(float x) {
    int c = (int)floorf(x * 8.0f) + 32;
    return min(GDIM - 1, max(0, c));
}
__device__ __forceinline__ int serp_col(int cx, int cy) {
    return cx * GDIM + ((cx & 1) ? (GDIM - 1 - cy) : cy);
}

// ---------------------------------------------------------------------------
// K0: zero histograms, counts, queue counter, output
// ---------------------------------------------------------------------------
__global__ void dacd_zero_kernel(float* __restrict__ out) {
    int t = blockIdx.x * blockDim.x + threadIdx.x;
    if (t < 2 * BATCH * NPTS) ((int*)g_cnt)[t] = 0;
    if (t < 2 * BATCH * NCOL) ((int*)g_hist)[t] = 0;
    if (t == 0) { out[0] = 0.0f; g_fbn = 0; }
}

// ---------------------------------------------------------------------------
// K1: serpentine column ids + histogram
// ---------------------------------------------------------------------------
__global__ void dacd_hist_kernel(const float* __restrict__ xyz1,
                                 const float* __restrict__ xyz2) {
    int t = blockIdx.x * blockDim.x + threadIdx.x;
    if (t >= 2 * BATCH * NPTS) return;
    const int a   = t / (BATCH * NPTS);
    const int rem = t % (BATCH * NPTS);
    const int b   = rem / NPTS;
    const int j   = rem % NPTS;
    const float* src = (a == 0) ? xyz1 : xyz2;
    float x = src[((size_t)b * NPTS + j) * 3 + 0];
    float y = src[((size_t)b * NPTS + j) * 3 + 1];
    int col = serp_col(cell_coord(x), cell_coord(y));
    g_colid[a][b][j] = col;
    atomicAdd(&g_hist[a][b][col], 1);
}

// ---------------------------------------------------------------------------
// K2: exclusive scan of 4096-entry histogram per set (8 blocks x 1024 thr)
// ---------------------------------------------------------------------------
__global__ void __launch_bounds__(1024)
dacd_scan_kernel() {
    const int a = blockIdx.x >> 2;
    const int b = blockIdx.x & 3;
    const int tid = threadIdx.x;
    __shared__ int sh[1024];

    int h[4];
    int tot = 0;
    #pragma unroll
    for (int i = 0; i < 4; i++) {
        h[i] = g_hist[a][b][tid * 4 + i];
        tot += h[i];
    }
    sh[tid] = tot;
    __syncthreads();
    #pragma unroll
    for (int off = 1; off < 1024; off <<= 1) {
        int v = (tid >= off) ? sh[tid - off] : 0;
        __syncthreads();
        sh[tid] += v;
        __syncthreads();
    }
    int base = sh[tid] - tot;
    #pragma unroll
    for (int i = 0; i < 4; i++) {
        g_start [a][b][tid * 4 + i] = base;
        g_cursor[a][b][tid * 4 + i] = base;
        base += h[i];
    }
    if (tid == 1023) g_start[a][b][NCOL] = base;   // == NPTS
}

// ---------------------------------------------------------------------------
// K3: scatter points into serpentine-column-sorted order
// ---------------------------------------------------------------------------
__global__ void dacd_scatter_kernel(const float* __restrict__ xyz1,
                                    const float* __restrict__ xyz2) {
    int t = blockIdx.x * blockDim.x + threadIdx.x;
    if (t >= 2 * BATCH * NPTS) return;
    const int a   = t / (BATCH * NPTS);
    const int rem = t % (BATCH * NPTS);
    const int b   = rem / NPTS;
    const int j   = rem % NPTS;
    const float* src = (a == 0) ? xyz1 : xyz2;
    float x = src[((size_t)b * NPTS + j) * 3 + 0];
    float y = src[((size_t)b * NPTS + j) * 3 + 1];
    float z = src[((size_t)b * NPTS + j) * 3 + 2];
    int col = g_colid[a][b][j];
    int pos = atomicAdd(&g_cursor[a][b][col], 1);
    g_pts [a][b][pos] = make_float4(x, y, z, x * x + y * y + z * z);
    g_orig[a][b][pos] = j;
}

// ---------------------------------------------------------------------------
// K4a: pass A — fixed rectangle (warp box + KRECT cells), one contiguous run
// per x-row. If a lane's true squared distance <= BOUND - eps it is provably
// the global NN (unscanned points differ by >= KRECT*CELLW in x or y; clamped
// border cells only push points farther). Converged lanes finalize; the rest
// are appended to the fallback queue.
// ---------------------------------------------------------------------------
__global__ void __launch_bounds__(256)
dacd_nn_grid_kernel() {
    const int lane  = threadIdx.x & 31;
    const int W     = blockIdx.x * 8 + (threadIdx.x >> 5);   // 0..2047
    const int dir   = W >> 10;
    const int b     = (W >> 8) & 3;
    const int chunk = W & 255;
    const int qarr  = 1 - dir;
    const int rarr  = dir;

    const int si = chunk * 32 + lane;
    const float4 q  = g_pts [qarr][b][si];
    const int    oi = g_orig[qarr][b][si];
    const float mx = -2.0f * q.x, my = -2.0f * q.y, mz = -2.0f * q.z;

    const int qcx = cell_coord(q.x);
    const int qcy = cell_coord(q.y);
    const int bx0 = (int)__reduce_min_sync(0xFFFFFFFFu, (unsigned)qcx);
    const int bx1 = (int)__reduce_max_sync(0xFFFFFFFFu, (unsigned)qcx);
    const int by0 = (int)__reduce_min_sync(0xFFFFFFFFu, (unsigned)qcy);
    const int by1 = (int)__reduce_max_sync(0xFFFFFFFFu, (unsigned)qcy);

    const int xlo = max(bx0 - KRECT, 0), xhi = min(bx1 + KRECT, GDIM - 1);
    const int ylo = max(by0 - KRECT, 0), yhi = min(by1 + KRECT, GDIM - 1);

    const float4* __restrict__ refs = &g_pts  [rarr][b][0];
    const int*    __restrict__ cs   = &g_start[rarr][b][0];

    float bestd = INFINITY;   // d' = |r|^2 - 2 q.r
    int   bestt = 0;

    #pragma unroll 1
    for (int cx = xlo; cx <= xhi; cx++) {
        int lo, hi;
        if (cx & 1) { lo = cx * GDIM + (GDIM - 1 - yhi); hi = cx * GDIM + (GDIM - 1 - ylo); }
        else        { lo = cx * GDIM + ylo;              hi = cx * GDIM + yhi; }
        const int s = cs[lo];
        const int e = cs[hi + 1];
        #pragma unroll 4
        for (int t = s; t < e; t++) {
            float4 v = __ldg(&refs[t]);
            float d = fmaf(mx, v.x, fmaf(my, v.y, fmaf(mz, v.z, v.w)));
            if (d < bestd) { bestd = d; bestt = t; }
        }
    }

    const float dtrue = q.w + bestd;
    const bool ok = dtrue <= (BOUND - 1e-4f);

    if (ok) {
        const int bj = g_orig[rarr][b][bestt];
        g_dist[dir][b][oi] = dtrue;
        g_idx [dir][b][oi] = bj;
        atomicAdd(&g_cnt[dir][b][bj], 1);
    }
    // compact append of non-converged lanes
    const unsigned vote = __ballot_sync(0xFFFFFFFFu, !ok);
    if (vote) {
        int base = 0;
        if (lane == 0) base = atomicAdd(&g_fbn, __popc(vote));
        base = __shfl_sync(0xFFFFFFFFu, base, 0);
        if (!ok) {
            int off = __popc(vote & ((1u << lane) - 1u));
            g_fbq[base + off] = (dir << 15) | (b << 13) | si;
        }
    }
}

// ---------------------------------------------------------------------------
// K4b: pass B — exact brute force for queued queries. One warp per queue item
// (grid-strided). Each lane scans 256 points; warp shuffle reduce for min
// (tie -> smaller sorted position, deterministic).
// ---------------------------------------------------------------------------
__global__ void __launch_bounds__(256)
dacd_nn_fallback_kernel() {
    const int lane = threadIdx.x & 31;
    const int wid  = blockIdx.x * 8 + (threadIdx.x >> 5);
    const int nw   = gridDim.x * 8;
    const int n    = g_fbn;

    for (int item = wid; item < n; item += nw) {
        const int pk  = g_fbq[item];
        const int dir = pk >> 15;
        const int b   = (pk >> 13) & 3;
        const int si  = pk & 0x1FFF;
        const int qarr = 1 - dir;
        const int rarr = dir;

        const float4 q  = g_pts [qarr][b][si];
        const int    oi = g_orig[qarr][b][si];
        const float mx = -2.0f * q.x, my = -2.0f * q.y, mz = -2.0f * q.z;

        const float4* __restrict__ refs = &g_pts[rarr][b][0];

        float bestd = INFINITY;
        int   bestt = 0;
        #pragma unroll 4
        for (int t = lane; t < NPTS; t += 32) {
            float4 v = __ldg(&refs[t]);
            float d = fmaf(mx, v.x, fmaf(my, v.y, fmaf(mz, v.z, v.w)));
            if (d < bestd) { bestd = d; bestt = t; }
        }
        // warp reduce (min d, tie -> min t)
        #pragma unroll
        for (int off = 16; off > 0; off >>= 1) {
            float od = __shfl_xor_sync(0xFFFFFFFFu, bestd, off);
            int   ot = __shfl_xor_sync(0xFFFFFFFFu, bestt, off);
            if (od < bestd || (od == bestd && ot < bestt)) { bestd = od; bestt = ot; }
        }
        if (lane == 0) {
            const int bj = g_orig[rarr][b][bestt];
            g_dist[dir][b][oi] = q.w + bestd;
            g_idx [dir][b][oi] = bj;
            atomicAdd(&g_cnt[dir][b][bj], 1);
        }
    }
}

// ---------------------------------------------------------------------------
// K5: density-aware weighting + reduction to scalar.
// frac_21 = 1.0 exactly; ceil(frac_21) = 1.
// weight1 = 1 / max(1/c + 1e-6, 1),  weight2 = 1 / (c + 1e-6)
// out = sum (1 - exp(-alpha*d) * w) / (2*B*N)
// ---------------------------------------------------------------------------
__global__ void __launch_bounds__(256)
dacd_loss_kernel(float* __restrict__ out) {
    const int t = blockIdx.x * blockDim.x + threadIdx.x;
    const int dir = t / (BATCH * NPTS);
    const int rem = t % (BATCH * NPTS);
    const int b = rem / NPTS;
    const int i = rem % NPTS;

    float dist = g_dist[dir][b][i];
    int   idx  = g_idx [dir][b][i];
    float c    = (float)g_cnt[dir][b][idx];

    float w;
    if (dir == 0) {
        w = 1.0f / fmaxf(1.0f / c + 1e-6f, 1.0f);
    } else {
        w = 1.0f / (c + 1e-6f);
    }

    float e = expf(-dist * ALPHA);
    float contrib = (1.0f - e * w) * (1.0f / (2.0f * BATCH * NPTS));

    #pragma unroll
    for (int off = 16; off > 0; off >>= 1)
        contrib += __shfl_down_sync(0xFFFFFFFFu, contrib, off);

    __shared__ float warp_sums[8];
    const int lane = threadIdx.x & 31;
    const int wid  = threadIdx.x >> 5;
    if (lane == 0) warp_sums[wid] = contrib;
    __syncthreads();

    if (wid == 0) {
        float s = (lane < 8) ? warp_sums[lane] : 0.0f;
        #pragma unroll
        for (int off = 4; off > 0; off >>= 1)
            s += __shfl_down_sync(0xFFFFFFFFu, s, off);
        if (lane == 0) atomicAdd(out, s);
    }
}

// ---------------------------------------------------------------------------
// Launch
// ---------------------------------------------------------------------------
extern "C" void kernel_launch(void* const* d_in, const int* in_sizes, int n_in,
                              void* d_out, int out_size) {
    const float* xyz1 = (const float*)d_in[0];  // prediction [4,8192,3]
    const float* xyz2 = (const float*)d_in[1];  // ground truth [4,8192,3]
    float* out = (float*)d_out;

    (void)in_sizes; (void)n_in; (void)out_size;

    const int total = 2 * BATCH * NPTS;          // 65536

    dacd_zero_kernel    <<<(total + 255) / 256, 256>>>(out);
    dacd_hist_kernel    <<<(total + 255) / 256, 256>>>(xyz1, xyz2);
    dacd_scan_kernel    <<<2 * BATCH, 1024>>>();
    dacd_scatter_kernel <<<(total + 255) / 256, 256>>>(xyz1, xyz2);

    dacd_nn_grid_kernel    <<<256, 256>>>();     // 2048 warps
    dacd_nn_fallback_kernel<<<128, 256>>>();     // 1024 warps, queue-strided

    dacd_loss_kernel<<<total / 256, 256>>>(out);
}